// round 14
// baseline (speedup 1.0000x reference)
#include <cuda_runtime.h>
#include <cuda_bf16.h>
#include <cstdint>
#include <math.h>

// ---------------- problem constants ----------------
#define BATCH 32
#define HW    1024
#define C     512
#define GROUPS 32
#define CPG   16
#define M_TOT (BATCH*HW)       // 32768
#define EPS   1e-6f
#define NQKV  1536

// ---------------- scratch ----------------
__device__ __nv_bfloat16 g_hn  [(long long)M_TOT * C];
__device__ __nv_bfloat16 g_qkv [(long long)M_TOT * NQKV];    // [row][q|k|v]
__device__ __nv_bfloat16 g_s   [(long long)BATCH * HW * HW]; // exp(scores), unnormalized
__device__ __nv_bfloat16 g_o   [(long long)M_TOT * C];
__device__ __nv_bfloat16 g_wqkv[(long long)C * NQKV];        // [k][q|k|v]
__device__ __nv_bfloat16 g_wp  [(long long)C * C];
__device__ float g_bqkv[NQKV];
__device__ float g_rowsum[BATCH * HW];

// ---------------- helpers ----------------
__device__ __forceinline__ uint32_t smem_u32(const void* p) {
    uint32_t a;
    asm("{ .reg .u64 t; cvta.to.shared.u64 t, %1; cvt.u32.u64 %0, t; }" : "=r"(a) : "l"(p));
    return a;
}
__device__ __forceinline__ void pdl_wait() {
#if __CUDA_ARCH__ >= 900
    cudaGridDependencySynchronize();
#endif
}
__device__ __forceinline__ void pdl_trigger() {
#if __CUDA_ARCH__ >= 900
    cudaTriggerProgrammaticLaunchCompletion();
#endif
}
// 2^t on the FMA pipe (no MUFU). deg-5 Taylor of 2^f on [0,1): rel err <= ~5e-5,
// far below bf16 storage rounding. t is bounded (|scores·scale| < ~40).
__device__ __forceinline__ float fast_exp2(float t) {
    float fi = floorf(t);
    float f  = t - fi;
    float p = fmaf(f, 0.0013333558f, 0.0096181291f);
    p = fmaf(f, p, 0.0555041087f);
    p = fmaf(f, p, 0.2402265070f);
    p = fmaf(f, p, 0.6931471806f);
    p = fmaf(f, p, 1.0f);
    return __int_as_float(((int)fi + 127) << 23) * p;
}
#define LDSM_X4(r0,r1,r2,r3,addr) \
    asm volatile("ldmatrix.sync.aligned.m8n8.x4.shared.b16 {%0,%1,%2,%3}, [%4];" \
        : "=r"(r0),"=r"(r1),"=r"(r2),"=r"(r3) : "r"(addr))
#define LDSM_X4T(r0,r1,r2,r3,addr) \
    asm volatile("ldmatrix.sync.aligned.m8n8.x4.trans.shared.b16 {%0,%1,%2,%3}, [%4];" \
        : "=r"(r0),"=r"(r1),"=r"(r2),"=r"(r3) : "r"(addr))
#define MMA_BF16(d, a, b) \
    asm volatile("mma.sync.aligned.m16n8k16.row.col.f32.bf16.bf16.f32 " \
        "{%0,%1,%2,%3}, {%4,%5,%6,%7}, {%8,%9}, {%0,%1,%2,%3};" \
        : "+f"((d)[0]), "+f"((d)[1]), "+f"((d)[2]), "+f"((d)[3]) \
        : "r"((a)[0]), "r"((a)[1]), "r"((a)[2]), "r"((a)[3]), "r"((b)[0]), "r"((b)[1]))
#define CP_ASYNC16(smem, gmem) \
    asm volatile("cp.async.cg.shared.global [%0], [%1], 16;" :: "r"(smem), "l"(gmem))
#define CP_COMMIT() asm volatile("cp.async.commit_group;" ::: "memory")
#define CP_WAIT1()  asm volatile("cp.async.wait_group 1;" ::: "memory")

// ---------------- merged prologue + groupnorm ----------------
__global__ __launch_bounds__(256)
void pro_gn_kernel(const float* __restrict__ x, const float* __restrict__ scale,
                   const float* __restrict__ bias, __nv_bfloat16* __restrict__ hn,
                   const float* __restrict__ wq, const float* __restrict__ wk,
                   const float* __restrict__ wv, __nv_bfloat16* __restrict__ wqkvo,
                   const float* __restrict__ bq, const float* __restrict__ bk,
                   const float* __restrict__ bv, float* __restrict__ bqkv,
                   const float* __restrict__ wp, __nv_bfloat16* __restrict__ wpo,
                   float* __restrict__ rs)
{
    const int blk = blockIdx.x;
    const int tid = threadIdx.x;
    if (blk < 512) {
        // ---- groupnorm over a 32-channel pair ----
        const int b = blk >> 4, gp = blk & 15;
        const float4* base4 = reinterpret_cast<const float4*>(x + (long long)b * HW * C + gp * 32);
        const int lane = tid & 31, wid = tid >> 5;
        const int grp = (tid >> 2) & 1;

        float s = 0.f, s2 = 0.f;
        for (int e = tid; e < HW * 8; e += 256) {
            int p = e >> 3, cc = e & 7;
            float4 v = base4[(long long)p * 128 + cc];
            s  += v.x + v.y + v.z + v.w;
            s2 += v.x * v.x + v.y * v.y + v.z * v.z + v.w * v.w;
        }
        s  += __shfl_xor_sync(0xffffffffu, s, 1);
        s2 += __shfl_xor_sync(0xffffffffu, s2, 1);
        s  += __shfl_xor_sync(0xffffffffu, s, 2);
        s2 += __shfl_xor_sync(0xffffffffu, s2, 2);
        s  += __shfl_xor_sync(0xffffffffu, s, 8);
        s2 += __shfl_xor_sync(0xffffffffu, s2, 8);
        s  += __shfl_xor_sync(0xffffffffu, s, 16);
        s2 += __shfl_xor_sync(0xffffffffu, s2, 16);

        __shared__ float red[2][2][8];
        __shared__ float mr[2][2];
        if (lane == 0)      { red[0][0][wid] = s; red[0][1][wid] = s2; }
        else if (lane == 4) { red[1][0][wid] = s; red[1][1][wid] = s2; }
        __syncthreads();
        if (tid < 2) {
            float ss = 0.f, ss2 = 0.f;
#pragma unroll
            for (int w = 0; w < 8; w++) { ss += red[tid][0][w]; ss2 += red[tid][1][w]; }
            float m = ss * (1.f / (HW * CPG));
            float var = ss2 * (1.f / (HW * CPG)) - m * m;
            mr[tid][0] = m; mr[tid][1] = rsqrtf(var + EPS);
        }
        __syncthreads();
        const float m = mr[grp][0], r = mr[grp][1];

        __nv_bfloat16* hbase = hn + (long long)b * HW * C + gp * 32;
        for (int e = tid; e < HW * 8; e += 256) {
            int p = e >> 3, cc = e & 7;
            float4 v  = base4[(long long)p * 128 + cc];
            float4 sc = reinterpret_cast<const float4*>(scale)[gp * 8 + cc];
            float4 bi = reinterpret_cast<const float4*>(bias)[gp * 8 + cc];
            __nv_bfloat162 h0 = __floats2bfloat162_rn((v.x - m) * r * sc.x + bi.x, (v.y - m) * r * sc.y + bi.y);
            __nv_bfloat162 h1 = __floats2bfloat162_rn((v.z - m) * r * sc.z + bi.z, (v.w - m) * r * sc.w + bi.w);
            __nv_bfloat162* hp = reinterpret_cast<__nv_bfloat162*>(hbase + (long long)p * C + cc * 4);
            hp[0] = h0; hp[1] = h1;
        }
    } else if (blk < 1280) {
        int i = (blk - 512) * 256 + tid;               // float4 over [512][1536]
        int row = i / (NQKV / 4);
        int col = (i % (NQKV / 4)) * 4;
        int sel = col >> 9;
        const float* src = (sel == 0) ? wq : (sel == 1) ? wk : wv;
        float4 v = *reinterpret_cast<const float4*>(src + (long long)row * C + (col & 511));
        __nv_bfloat162* h2 = reinterpret_cast<__nv_bfloat162*>(wqkvo) + i * 2;
        h2[0] = __floats2bfloat162_rn(v.x, v.y);
        h2[1] = __floats2bfloat162_rn(v.z, v.w);
    } else if (blk < 1536) {
        int i = (blk - 1280) * 256 + tid;              // float4 over [512][512]
        float4 v = reinterpret_cast<const float4*>(wp)[i];
        __nv_bfloat162* h2 = reinterpret_cast<__nv_bfloat162*>(wpo) + i * 2;
        h2[0] = __floats2bfloat162_rn(v.x, v.y);
        h2[1] = __floats2bfloat162_rn(v.z, v.w);
        if (i < NQKV) {
            int sel = i >> 9;
            const float* src = (sel == 0) ? bq : (sel == 1) ? bk : bv;
            bqkv[i] = src[i & 511];
        }
    } else {
        int i = (blk - 1536) * 256 + tid;
        if (i < BATCH * HW) rs[i] = 0.f;
    }
    pdl_trigger();
}

// ---------------- HMMA GEMM (256 threads, 8 warps of 32x64, 3-stage, 1 sync/iter) ----------------
// TB=false (NT): D = A[M,K] @ B[N,K]^T.  TB=true (NN): D = A[M,K] @ B[K,N].
// MODE 0: bf16 out + bias.          MODE 1: bf16 out = 2^(acc*scale) + rowsum atomics
//                                            (scale carries log2e — exp on the FMA pipe).
// MODE 2: fp32 out + bias + residual.  MODE 3: bf16 out = acc / rowsum[row].
#define A_STRIDE 144u
#define BNN_STRIDE 272u
#define BOFF  18432u
#define STAGE 36864u
#define NSTG  3

template<bool TB, int MODE>
__global__ void __launch_bounds__(256, 2)
mma_gemm(const __nv_bfloat16* __restrict__ A, const __nv_bfloat16* __restrict__ B,
         const float* __restrict__ bias, const float* __restrict__ residual,
         float* __restrict__ rowsum,
         void* __restrict__ Out, int K, int lda, int ldb, int Ntot,
         float scale, long long sA, long long sB, long long sO)
{
    extern __shared__ char dyn[];
    const uint32_t smem0 = smem_u32(dyn);
    const uint32_t smemEnd = smem0 + NSTG * STAGE;

    const int tid = threadIdx.x, lane = tid & 31, wid = tid >> 5;
    const int warp_m = wid & 3, warp_n = wid >> 2;
    const int bx = blockIdx.x, by = blockIdx.y, bz = blockIdx.z;

    const int NC = K >> 6;

    float acc[2][8][4];
#pragma unroll
    for (int mt = 0; mt < 2; mt++)
#pragma unroll
        for (int nt = 0; nt < 8; nt++)
#pragma unroll
            for (int e = 0; e < 4; e++) acc[mt][nt][e] = 0.f;

    // ----- incremental global pointers -----
    const char* pA = (const char*)(A + bz * sA)
                   + ((long long)(by * 128 + (tid >> 3)) * lda) * 2 + (tid & 7) * 16;
    const long long aRep = (long long)32 * lda * 2;   // +32 rows
    const char* pB;
    long long bRep;
    if (TB) {
        pB = (const char*)(B + bz * sB) + ((long long)(tid >> 4) * ldb + bx * 128) * 2 + (tid & 15) * 16;
        bRep = (long long)16 * ldb * 2;               // +16 k-rows
    } else {
        pB = (const char*)(B + bz * sB) + ((long long)(bx * 128 + (tid >> 3)) * ldb) * 2 + (tid & 7) * 16;
        bRep = (long long)32 * ldb * 2;               // +32 n-rows
    }
    const long long aAdv = 128;                        // bytes per k-chunk
    const long long bAdv = TB ? (long long)64 * ldb * 2 : 128;

    // ----- smem store offsets (per-thread constants) -----
    const uint32_t sAoff = (uint32_t)(tid >> 3) * A_STRIDE + (uint32_t)(tid & 7) * 16;
    const uint32_t sBoff = TB
        ? BOFF + (uint32_t)(tid >> 4) * BNN_STRIDE + (uint32_t)(tid & 15) * 16
        : BOFF + (uint32_t)(tid >> 3) * A_STRIDE + (uint32_t)(tid & 7) * 16;
    constexpr uint32_t sBrep = TB ? 16u * BNN_STRIDE : 32u * A_STRIDE;

    uint32_t stLd = smem0;    // stage base for next load
    auto load_chunk = [&]() {
#pragma unroll
        for (int rep = 0; rep < 4; rep++)
            CP_ASYNC16(stLd + sAoff + (uint32_t)rep * (32u * A_STRIDE), pA + rep * aRep);
#pragma unroll
        for (int rep = 0; rep < 4; rep++)
            CP_ASYNC16(stLd + sBoff + (uint32_t)rep * sBrep, pB + rep * bRep);
        CP_COMMIT();
        pA += aAdv; pB += bAdv;
        stLd += STAGE; if (stLd == smemEnd) stLd = smem0;
    };

    // PDL: block until upstream writes are visible, then start loading.
    pdl_wait();

    load_chunk();
    load_chunk();

    const int lan15 = lane & 15;
    const int hi8   = (lane >> 4) << 3;

    uint32_t smCur = smem0;
    for (int i = 0; i < NC; ++i) {
        CP_WAIT1();
        __syncthreads();
        const uint32_t smA = smCur;
        const uint32_t smB = smCur + BOFF;
#pragma unroll
        for (int ks = 0; ks < 4; ks++) {
            uint32_t a[2][4];
#pragma unroll
            for (int mt = 0; mt < 2; mt++) {
                uint32_t ad = smA + (uint32_t)(warp_m * 32 + mt * 16 + lan15) * A_STRIDE
                                  + (uint32_t)(ks * 16 + hi8) * 2;
                LDSM_X4(a[mt][0], a[mt][1], a[mt][2], a[mt][3], ad);
            }
            uint32_t b[8][2];
            if (TB) {
#pragma unroll
                for (int np = 0; np < 4; np++) {
                    uint32_t ad = smB + (uint32_t)(ks * 16 + lan15) * BNN_STRIDE
                                      + (uint32_t)(warp_n * 64 + np * 16 + hi8) * 2;
                    uint32_t r0, r1, r2, r3;
                    LDSM_X4T(r0, r1, r2, r3, ad);
                    b[2*np][0] = r0; b[2*np][1] = r1;
                    b[2*np+1][0] = r2; b[2*np+1][1] = r3;
                }
            } else {
#pragma unroll
                for (int np = 0; np < 4; np++) {
                    uint32_t ad = smB + (uint32_t)(warp_n * 64 + np * 16 + lan15) * A_STRIDE
                                      + (uint32_t)(ks * 16 + hi8) * 2;
                    uint32_t r0, r1, r2, r3;
                    LDSM_X4(r0, r1, r2, r3, ad);
                    b[2*np][0] = r0; b[2*np][1] = r2;
                    b[2*np+1][0] = r1; b[2*np+1][1] = r3;
                }
            }
#pragma unroll
            for (int mt = 0; mt < 2; mt++)
#pragma unroll
                for (int nt = 0; nt < 8; nt++)
                    MMA_BF16(acc[mt][nt], a[mt], b[nt]);
        }
        smCur += STAGE; if (smCur == smemEnd) smCur = smem0;
        // load AFTER compute (R9 proven ordering)
        if (i + 2 < NC) load_chunk();
        else CP_COMMIT();
    }

    // allow the dependent kernel to launch while epilogues run
    pdl_trigger();

    // ---------------- epilogue (direct stores) ----------------
    const int group = lane >> 2, tig = lane & 3;
#pragma unroll
    for (int mt = 0; mt < 2; mt++) {
        const int r0 = by * 128 + warp_m * 32 + mt * 16 + group;
        if (MODE == 1) {
            __nv_bfloat16* op = (__nv_bfloat16*)Out + bz * sO;
            float rs0 = 0.f, rs1 = 0.f;
#pragma unroll
            for (int nt = 0; nt < 8; nt++) {
                const int cg = bx * 128 + warp_n * 64 + nt * 8 + tig * 2;
                float e0 = fast_exp2(acc[mt][nt][0] * scale);
                float e1 = fast_exp2(acc[mt][nt][1] * scale);
                float e2 = fast_exp2(acc[mt][nt][2] * scale);
                float e3 = fast_exp2(acc[mt][nt][3] * scale);
                *(__nv_bfloat162*)(op + (long long)r0 * Ntot + cg)       = __floats2bfloat162_rn(e0, e1);
                *(__nv_bfloat162*)(op + (long long)(r0 + 8) * Ntot + cg) = __floats2bfloat162_rn(e2, e3);
                rs0 += e0 + e1; rs1 += e2 + e3;
            }
            rs0 += __shfl_xor_sync(0xffffffffu, rs0, 1);
            rs0 += __shfl_xor_sync(0xffffffffu, rs0, 2);
            rs1 += __shfl_xor_sync(0xffffffffu, rs1, 1);
            rs1 += __shfl_xor_sync(0xffffffffu, rs1, 2);
            if (tig == 0) {
                atomicAdd(rowsum + bz * HW + r0, rs0);
                atomicAdd(rowsum + bz * HW + r0 + 8, rs1);
            }
        } else if (MODE == 3) {
            const float inv0 = 1.f / rowsum[bz * HW + r0];
            const float inv1 = 1.f / rowsum[bz * HW + r0 + 8];
            __nv_bfloat16* op = (__nv_bfloat16*)Out + bz * sO;
#pragma unroll
            for (int nt = 0; nt < 8; nt++) {
                const int cg = bx * 128 + warp_n * 64 + nt * 8 + tig * 2;
                *(__nv_bfloat162*)(op + (long long)r0 * Ntot + cg) =
                    __floats2bfloat162_rn(acc[mt][nt][0] * inv0, acc[mt][nt][1] * inv0);
                *(__nv_bfloat162*)(op + (long long)(r0 + 8) * Ntot + cg) =
                    __floats2bfloat162_rn(acc[mt][nt][2] * inv1, acc[mt][nt][3] * inv1);
            }
        } else if (MODE == 2) {
#pragma unroll
            for (int nt = 0; nt < 8; nt++) {
                const int cg = bx * 128 + warp_n * 64 + nt * 8 + tig * 2;
                float b0 = bias[cg], b1 = bias[cg + 1];
                {
                    long long idx = bz * sO + (long long)r0 * Ntot + cg;
                    const float2 rv = *(const float2*)(residual + idx);
                    float2 v = { acc[mt][nt][0] + b0 + rv.x,
                                 acc[mt][nt][1] + b1 + rv.y };
                    *(float2*)((float*)Out + idx) = v;
                }
                {
                    long long idx = bz * sO + (long long)(r0 + 8) * Ntot + cg;
                    const float2 rv = *(const float2*)(residual + idx);
                    float2 v = { acc[mt][nt][2] + b0 + rv.x,
                                 acc[mt][nt][3] + b1 + rv.y };
                    *(float2*)((float*)Out + idx) = v;
                }
            }
        } else {
            __nv_bfloat16* op = (__nv_bfloat16*)Out + bz * sO;
#pragma unroll
            for (int nt = 0; nt < 8; nt++) {
                const int cg = bx * 128 + warp_n * 64 + nt * 8 + tig * 2;
                float b0 = bias[cg], b1 = bias[cg + 1];
                *(__nv_bfloat162*)(op + (long long)r0 * Ntot + cg) =
                    __floats2bfloat162_rn(acc[mt][nt][0] + b0, acc[mt][nt][1] + b1);
                *(__nv_bfloat162*)(op + (long long)(r0 + 8) * Ntot + cg) =
                    __floats2bfloat162_rn(acc[mt][nt][2] + b0, acc[mt][nt][3] + b1);
            }
        }
    }
}

// ---------------- PDL launch helper ----------------
template<typename... Args>
static void launch_pdl(void (*kern)(Args...), dim3 grid, dim3 block, size_t smem,
                       Args... args)
{
    cudaLaunchConfig_t cfg = {};
    cfg.gridDim = grid;
    cfg.blockDim = block;
    cfg.dynamicSmemBytes = smem;
    cudaLaunchAttribute attr[1];
    attr[0].id = cudaLaunchAttributeProgrammaticStreamSerialization;
    attr[0].val.programmaticStreamSerializationAllowed = 1;
    cfg.attrs = attr;
    cfg.numAttrs = 1;
    cudaLaunchKernelEx(&cfg, kern, args...);
}

// ---------------- launch ----------------
extern "C" void kernel_launch(void* const* d_in, const int* in_sizes, int n_in,
                              void* d_out, int out_size)
{
    const float* x  = (const float*)d_in[0];
    const float* ns = (const float*)d_in[1];
    const float* nb = (const float*)d_in[2];
    const float* wq = (const float*)d_in[3];
    const float* bq = (const float*)d_in[4];
    const float* wk = (const float*)d_in[5];
    const float* bk = (const float*)d_in[6];
    const float* wv = (const float*)d_in[7];
    const float* bv = (const float*)d_in[8];
    const float* wp = (const float*)d_in[9];
    const float* bp = (const float*)d_in[10];
    float* out = (float*)d_out;

    __nv_bfloat16 *hn, *qkv, *s, *o, *wqkvB, *wpB;
    float *bqkv, *rs;
    cudaGetSymbolAddress((void**)&hn,    g_hn);
    cudaGetSymbolAddress((void**)&qkv,   g_qkv);
    cudaGetSymbolAddress((void**)&s,     g_s);
    cudaGetSymbolAddress((void**)&o,     g_o);
    cudaGetSymbolAddress((void**)&wqkvB, g_wqkv);
    cudaGetSymbolAddress((void**)&wpB,   g_wp);
    cudaGetSymbolAddress((void**)&bqkv,  g_bqkv);
    cudaGetSymbolAddress((void**)&rs,    g_rowsum);

    const int SMEM = NSTG * STAGE;   // 110592
    cudaFuncSetAttribute(mma_gemm<true, 0>,  cudaFuncAttributeMaxDynamicSharedMemorySize, SMEM);
    cudaFuncSetAttribute(mma_gemm<false, 1>, cudaFuncAttributeMaxDynamicSharedMemorySize, SMEM);
    cudaFuncSetAttribute(mma_gemm<true, 2>,  cudaFuncAttributeMaxDynamicSharedMemorySize, SMEM);
    cudaFuncSetAttribute(mma_gemm<true, 3>,  cudaFuncAttributeMaxDynamicSharedMemorySize, SMEM);

    // merged prologue + groupnorm (one launch; gn blocks first = long pole)
    pro_gn_kernel<<<1664, 256>>>(x, ns, nb, hn,
                                 wq, wk, wv, wqkvB,
                                 bq, bk, bv, bqkv,
                                 wp, wpB, rs);

    const __nv_bfloat16* q = qkv;
    const __nv_bfloat16* k = qkv + 512;
    const __nv_bfloat16* v = qkv + 1024;
    const long long sQKV = (long long)HW * NQKV;

    // fused qkv projection: [32768,512] @ [512,1536]
    launch_pdl(mma_gemm<true, 0>, dim3(NQKV / 128, M_TOT / 128, 1), dim3(256), (size_t)SMEM,
               (const __nv_bfloat16*)hn, (const __nv_bfloat16*)wqkvB,
               (const float*)bqkv, (const float*)nullptr, (float*)nullptr,
               (void*)qkv, (int)C, (int)C, (int)NQKV, (int)NQKV,
               1.f, 0LL, 0LL, 0LL);

    // exp-scores = 2^(q @ k^T * c^-0.5 * log2e), rowsum via atomics
    const float sc_log2e = (1.f / sqrtf((float)C)) * 1.4426950408889634f;
    launch_pdl(mma_gemm<false, 1>, dim3(HW / 128, HW / 128, BATCH), dim3(256), (size_t)SMEM,
               q, k, (const float*)nullptr, (const float*)nullptr, rs,
               (void*)s, (int)C, (int)NQKV, (int)NQKV, (int)HW,
               sc_log2e, sQKV, sQKV, (long long)HW * HW);

    // o = (expS @ v) / Z
    launch_pdl(mma_gemm<true, 3>, dim3(C / 128, HW / 128, BATCH), dim3(256), (size_t)SMEM,
               (const __nv_bfloat16*)s, v, (const float*)nullptr, (const float*)nullptr, rs,
               (void*)o, (int)HW, (int)HW, (int)NQKV, (int)C,
               1.f, (long long)HW * HW, sQKV, (long long)HW * C);

    // out = o @ wp + bp + x
    launch_pdl(mma_gemm<true, 2>, dim3(C / 128, M_TOT / 128, 1), dim3(256), (size_t)SMEM,
               (const __nv_bfloat16*)o, (const __nv_bfloat16*)wpB,
               bp, x, (float*)nullptr,
               (void*)out, (int)C, (int)C, (int)C, (int)C,
               1.f, 0LL, 0LL, 0LL);
}

// round 15
// speedup vs baseline: 1.0115x; 1.0115x over previous
#include <cuda_runtime.h>
#include <cuda_bf16.h>
#include <cstdint>
#include <math.h>

// ---------------- problem constants ----------------
#define BATCH 32
#define HW    1024
#define C     512
#define GROUPS 32
#define CPG   16
#define M_TOT (BATCH*HW)       // 32768
#define EPS   1e-6f
#define NQKV  1536

// ---------------- scratch ----------------
__device__ __nv_bfloat16 g_hn  [(long long)M_TOT * C];
__device__ __nv_bfloat16 g_qkv [(long long)M_TOT * NQKV];    // [row][q|k|v]
__device__ __nv_bfloat16 g_s   [(long long)BATCH * HW * HW]; // exp(scores), unnormalized
__device__ __nv_bfloat16 g_o   [(long long)M_TOT * C];
__device__ __nv_bfloat16 g_wqkv[(long long)C * NQKV];        // [k][q|k|v]
__device__ __nv_bfloat16 g_wp  [(long long)C * C];
__device__ float g_bqkv[NQKV];
__device__ float g_rowsum[BATCH * HW];

// ---------------- helpers ----------------
__device__ __forceinline__ uint32_t smem_u32(const void* p) {
    uint32_t a;
    asm("{ .reg .u64 t; cvta.to.shared.u64 t, %1; cvt.u32.u64 %0, t; }" : "=r"(a) : "l"(p));
    return a;
}
__device__ __forceinline__ void pdl_wait() {
#if __CUDA_ARCH__ >= 900
    cudaGridDependencySynchronize();
#endif
}
__device__ __forceinline__ void pdl_trigger() {
#if __CUDA_ARCH__ >= 900
    cudaTriggerProgrammaticLaunchCompletion();
#endif
}
#define LDSM_X4(r0,r1,r2,r3,addr) \
    asm volatile("ldmatrix.sync.aligned.m8n8.x4.shared.b16 {%0,%1,%2,%3}, [%4];" \
        : "=r"(r0),"=r"(r1),"=r"(r2),"=r"(r3) : "r"(addr))
#define LDSM_X4T(r0,r1,r2,r3,addr) \
    asm volatile("ldmatrix.sync.aligned.m8n8.x4.trans.shared.b16 {%0,%1,%2,%3}, [%4];" \
        : "=r"(r0),"=r"(r1),"=r"(r2),"=r"(r3) : "r"(addr))
#define MMA_BF16(d, a, b) \
    asm volatile("mma.sync.aligned.m16n8k16.row.col.f32.bf16.bf16.f32 " \
        "{%0,%1,%2,%3}, {%4,%5,%6,%7}, {%8,%9}, {%0,%1,%2,%3};" \
        : "+f"((d)[0]), "+f"((d)[1]), "+f"((d)[2]), "+f"((d)[3]) \
        : "r"((a)[0]), "r"((a)[1]), "r"((a)[2]), "r"((a)[3]), "r"((b)[0]), "r"((b)[1]))
#define CP_ASYNC16(smem, gmem) \
    asm volatile("cp.async.cg.shared.global [%0], [%1], 16;" :: "r"(smem), "l"(gmem))
#define CP_COMMIT() asm volatile("cp.async.commit_group;" ::: "memory")
#define CP_WAIT1()  asm volatile("cp.async.wait_group 1;" ::: "memory")

// ---------------- merged prologue + groupnorm ----------------
__global__ __launch_bounds__(256)
void pro_gn_kernel(const float* __restrict__ x, const float* __restrict__ scale,
                   const float* __restrict__ bias, __nv_bfloat16* __restrict__ hn,
                   const float* __restrict__ wq, const float* __restrict__ wk,
                   const float* __restrict__ wv, __nv_bfloat16* __restrict__ wqkvo,
                   const float* __restrict__ bq, const float* __restrict__ bk,
                   const float* __restrict__ bv, float* __restrict__ bqkv,
                   const float* __restrict__ wp, __nv_bfloat16* __restrict__ wpo,
                   float* __restrict__ rs)
{
    const int blk = blockIdx.x;
    const int tid = threadIdx.x;
    if (blk < 512) {
        // ---- groupnorm over a 32-channel pair ----
        const int b = blk >> 4, gp = blk & 15;
        const float4* base4 = reinterpret_cast<const float4*>(x + (long long)b * HW * C + gp * 32);
        const int lane = tid & 31, wid = tid >> 5;
        const int grp = (tid >> 2) & 1;

        float s = 0.f, s2 = 0.f;
        for (int e = tid; e < HW * 8; e += 256) {
            int p = e >> 3, cc = e & 7;
            float4 v = base4[(long long)p * 128 + cc];
            s  += v.x + v.y + v.z + v.w;
            s2 += v.x * v.x + v.y * v.y + v.z * v.z + v.w * v.w;
        }
        s  += __shfl_xor_sync(0xffffffffu, s, 1);
        s2 += __shfl_xor_sync(0xffffffffu, s2, 1);
        s  += __shfl_xor_sync(0xffffffffu, s, 2);
        s2 += __shfl_xor_sync(0xffffffffu, s2, 2);
        s  += __shfl_xor_sync(0xffffffffu, s, 8);
        s2 += __shfl_xor_sync(0xffffffffu, s2, 8);
        s  += __shfl_xor_sync(0xffffffffu, s, 16);
        s2 += __shfl_xor_sync(0xffffffffu, s2, 16);

        __shared__ float red[2][2][8];
        __shared__ float mr[2][2];
        if (lane == 0)      { red[0][0][wid] = s; red[0][1][wid] = s2; }
        else if (lane == 4) { red[1][0][wid] = s; red[1][1][wid] = s2; }
        __syncthreads();
        if (tid < 2) {
            float ss = 0.f, ss2 = 0.f;
#pragma unroll
            for (int w = 0; w < 8; w++) { ss += red[tid][0][w]; ss2 += red[tid][1][w]; }
            float m = ss * (1.f / (HW * CPG));
            float var = ss2 * (1.f / (HW * CPG)) - m * m;
            mr[tid][0] = m; mr[tid][1] = rsqrtf(var + EPS);
        }
        __syncthreads();
        const float m = mr[grp][0], r = mr[grp][1];

        __nv_bfloat16* hbase = hn + (long long)b * HW * C + gp * 32;
        for (int e = tid; e < HW * 8; e += 256) {
            int p = e >> 3, cc = e & 7;
            float4 v  = base4[(long long)p * 128 + cc];
            float4 sc = reinterpret_cast<const float4*>(scale)[gp * 8 + cc];
            float4 bi = reinterpret_cast<const float4*>(bias)[gp * 8 + cc];
            __nv_bfloat162 h0 = __floats2bfloat162_rn((v.x - m) * r * sc.x + bi.x, (v.y - m) * r * sc.y + bi.y);
            __nv_bfloat162 h1 = __floats2bfloat162_rn((v.z - m) * r * sc.z + bi.z, (v.w - m) * r * sc.w + bi.w);
            __nv_bfloat162* hp = reinterpret_cast<__nv_bfloat162*>(hbase + (long long)p * C + cc * 4);
            hp[0] = h0; hp[1] = h1;
        }
    } else if (blk < 1280) {
        int i = (blk - 512) * 256 + tid;               // float4 over [512][1536]
        int row = i / (NQKV / 4);
        int col = (i % (NQKV / 4)) * 4;
        int sel = col >> 9;
        const float* src = (sel == 0) ? wq : (sel == 1) ? wk : wv;
        float4 v = *reinterpret_cast<const float4*>(src + (long long)row * C + (col & 511));
        __nv_bfloat162* h2 = reinterpret_cast<__nv_bfloat162*>(wqkvo) + i * 2;
        h2[0] = __floats2bfloat162_rn(v.x, v.y);
        h2[1] = __floats2bfloat162_rn(v.z, v.w);
    } else if (blk < 1536) {
        int i = (blk - 1280) * 256 + tid;              // float4 over [512][512]
        float4 v = reinterpret_cast<const float4*>(wp)[i];
        __nv_bfloat162* h2 = reinterpret_cast<__nv_bfloat162*>(wpo) + i * 2;
        h2[0] = __floats2bfloat162_rn(v.x, v.y);
        h2[1] = __floats2bfloat162_rn(v.z, v.w);
        if (i < NQKV) {
            int sel = i >> 9;
            const float* src = (sel == 0) ? bq : (sel == 1) ? bk : bv;
            bqkv[i] = src[i & 511];
        }
    } else {
        int i = (blk - 1536) * 256 + tid;
        if (i < BATCH * HW) rs[i] = 0.f;
    }
    pdl_trigger();
}

// ---------------- HMMA GEMM (256 threads, 8 warps of 32x64, 3-stage, 1 sync/iter) ----------------
// TB=false (NT): D = A[M,K] @ B[N,K]^T.  TB=true (NN): D = A[M,K] @ B[K,N].
// MODE 0: bf16 out + bias.          MODE 1: bf16 out = exp2(acc*scale) + rowsum atomics
//                                            (scale carries log2e; exp2f = bare MUFU.EX2).
// MODE 2: fp32 out + bias + residual.  MODE 3: bf16 out = acc / rowsum[row].
#define A_STRIDE 144u
#define BNN_STRIDE 272u
#define BOFF  18432u
#define STAGE 36864u
#define NSTG  3

template<bool TB, int MODE>
__global__ void __launch_bounds__(256, 2)
mma_gemm(const __nv_bfloat16* __restrict__ A, const __nv_bfloat16* __restrict__ B,
         const float* __restrict__ bias, const float* __restrict__ residual,
         float* __restrict__ rowsum,
         void* __restrict__ Out, int K, int lda, int ldb, int Ntot,
         float scale, long long sA, long long sB, long long sO)
{
    extern __shared__ char dyn[];
    const uint32_t smem0 = smem_u32(dyn);
    const uint32_t smemEnd = smem0 + NSTG * STAGE;

    const int tid = threadIdx.x, lane = tid & 31, wid = tid >> 5;
    const int warp_m = wid & 3, warp_n = wid >> 2;
    const int bx = blockIdx.x, by = blockIdx.y, bz = blockIdx.z;

    const int NC = K >> 6;

    float acc[2][8][4];
#pragma unroll
    for (int mt = 0; mt < 2; mt++)
#pragma unroll
        for (int nt = 0; nt < 8; nt++)
#pragma unroll
            for (int e = 0; e < 4; e++) acc[mt][nt][e] = 0.f;

    // ----- incremental global pointers -----
    const char* pA = (const char*)(A + bz * sA)
                   + ((long long)(by * 128 + (tid >> 3)) * lda) * 2 + (tid & 7) * 16;
    const long long aRep = (long long)32 * lda * 2;   // +32 rows
    const char* pB;
    long long bRep;
    if (TB) {
        pB = (const char*)(B + bz * sB) + ((long long)(tid >> 4) * ldb + bx * 128) * 2 + (tid & 15) * 16;
        bRep = (long long)16 * ldb * 2;               // +16 k-rows
    } else {
        pB = (const char*)(B + bz * sB) + ((long long)(bx * 128 + (tid >> 3)) * ldb) * 2 + (tid & 7) * 16;
        bRep = (long long)32 * ldb * 2;               // +32 n-rows
    }
    const long long aAdv = 128;                        // bytes per k-chunk
    const long long bAdv = TB ? (long long)64 * ldb * 2 : 128;

    // ----- smem store offsets (per-thread constants) -----
    const uint32_t sAoff = (uint32_t)(tid >> 3) * A_STRIDE + (uint32_t)(tid & 7) * 16;
    const uint32_t sBoff = TB
        ? BOFF + (uint32_t)(tid >> 4) * BNN_STRIDE + (uint32_t)(tid & 15) * 16
        : BOFF + (uint32_t)(tid >> 3) * A_STRIDE + (uint32_t)(tid & 7) * 16;
    constexpr uint32_t sBrep = TB ? 16u * BNN_STRIDE : 32u * A_STRIDE;

    uint32_t stLd = smem0;    // stage base for next load
    auto load_chunk = [&]() {
#pragma unroll
        for (int rep = 0; rep < 4; rep++)
            CP_ASYNC16(stLd + sAoff + (uint32_t)rep * (32u * A_STRIDE), pA + rep * aRep);
#pragma unroll
        for (int rep = 0; rep < 4; rep++)
            CP_ASYNC16(stLd + sBoff + (uint32_t)rep * sBrep, pB + rep * bRep);
        CP_COMMIT();
        pA += aAdv; pB += bAdv;
        stLd += STAGE; if (stLd == smemEnd) stLd = smem0;
    };

    // PDL: block until upstream writes are visible, then start loading.
    pdl_wait();

    load_chunk();
    load_chunk();

    const int lan15 = lane & 15;
    const int hi8   = (lane >> 4) << 3;

    uint32_t smCur = smem0;
    for (int i = 0; i < NC; ++i) {
        CP_WAIT1();
        __syncthreads();
        const uint32_t smA = smCur;
        const uint32_t smB = smCur + BOFF;
#pragma unroll
        for (int ks = 0; ks < 4; ks++) {
            uint32_t a[2][4];
#pragma unroll
            for (int mt = 0; mt < 2; mt++) {
                uint32_t ad = smA + (uint32_t)(warp_m * 32 + mt * 16 + lan15) * A_STRIDE
                                  + (uint32_t)(ks * 16 + hi8) * 2;
                LDSM_X4(a[mt][0], a[mt][1], a[mt][2], a[mt][3], ad);
            }
            uint32_t b[8][2];
            if (TB) {
#pragma unroll
                for (int np = 0; np < 4; np++) {
                    uint32_t ad = smB + (uint32_t)(ks * 16 + lan15) * BNN_STRIDE
                                      + (uint32_t)(warp_n * 64 + np * 16 + hi8) * 2;
                    uint32_t r0, r1, r2, r3;
                    LDSM_X4T(r0, r1, r2, r3, ad);
                    b[2*np][0] = r0; b[2*np][1] = r1;
                    b[2*np+1][0] = r2; b[2*np+1][1] = r3;
                }
            } else {
#pragma unroll
                for (int np = 0; np < 4; np++) {
                    uint32_t ad = smB + (uint32_t)(warp_n * 64 + np * 16 + lan15) * A_STRIDE
                                      + (uint32_t)(ks * 16 + hi8) * 2;
                    uint32_t r0, r1, r2, r3;
                    LDSM_X4(r0, r1, r2, r3, ad);
                    b[2*np][0] = r0; b[2*np][1] = r2;
                    b[2*np+1][0] = r1; b[2*np+1][1] = r3;
                }
            }
#pragma unroll
            for (int mt = 0; mt < 2; mt++)
#pragma unroll
                for (int nt = 0; nt < 8; nt++)
                    MMA_BF16(acc[mt][nt], a[mt], b[nt]);
        }
        smCur += STAGE; if (smCur == smemEnd) smCur = smem0;
        // load AFTER compute (R9 proven ordering)
        if (i + 2 < NC) load_chunk();
        else CP_COMMIT();
    }

    // allow the dependent kernel to launch while epilogues run
    pdl_trigger();

    // ---------------- epilogue (direct stores) ----------------
    const int group = lane >> 2, tig = lane & 3;
#pragma unroll
    for (int mt = 0; mt < 2; mt++) {
        const int r0 = by * 128 + warp_m * 32 + mt * 16 + group;
        if (MODE == 1) {
            __nv_bfloat16* op = (__nv_bfloat16*)Out + bz * sO;
            float rs0 = 0.f, rs1 = 0.f;
#pragma unroll
            for (int nt = 0; nt < 8; nt++) {
                const int cg = bx * 128 + warp_n * 64 + nt * 8 + tig * 2;
                float e0 = exp2f(acc[mt][nt][0] * scale);
                float e1 = exp2f(acc[mt][nt][1] * scale);
                float e2 = exp2f(acc[mt][nt][2] * scale);
                float e3 = exp2f(acc[mt][nt][3] * scale);
                *(__nv_bfloat162*)(op + (long long)r0 * Ntot + cg)       = __floats2bfloat162_rn(e0, e1);
                *(__nv_bfloat162*)(op + (long long)(r0 + 8) * Ntot + cg) = __floats2bfloat162_rn(e2, e3);
                rs0 += e0 + e1; rs1 += e2 + e3;
            }
            rs0 += __shfl_xor_sync(0xffffffffu, rs0, 1);
            rs0 += __shfl_xor_sync(0xffffffffu, rs0, 2);
            rs1 += __shfl_xor_sync(0xffffffffu, rs1, 1);
            rs1 += __shfl_xor_sync(0xffffffffu, rs1, 2);
            if (tig == 0) {
                atomicAdd(rowsum + bz * HW + r0, rs0);
                atomicAdd(rowsum + bz * HW + r0 + 8, rs1);
            }
        } else if (MODE == 3) {
            const float inv0 = 1.f / rowsum[bz * HW + r0];
            const float inv1 = 1.f / rowsum[bz * HW + r0 + 8];
            __nv_bfloat16* op = (__nv_bfloat16*)Out + bz * sO;
#pragma unroll
            for (int nt = 0; nt < 8; nt++) {
                const int cg = bx * 128 + warp_n * 64 + nt * 8 + tig * 2;
                *(__nv_bfloat162*)(op + (long long)r0 * Ntot + cg) =
                    __floats2bfloat162_rn(acc[mt][nt][0] * inv0, acc[mt][nt][1] * inv0);
                *(__nv_bfloat162*)(op + (long long)(r0 + 8) * Ntot + cg) =
                    __floats2bfloat162_rn(acc[mt][nt][2] * inv1, acc[mt][nt][3] * inv1);
            }
        } else if (MODE == 2) {
#pragma unroll
            for (int nt = 0; nt < 8; nt++) {
                const int cg = bx * 128 + warp_n * 64 + nt * 8 + tig * 2;
                float b0 = bias[cg], b1 = bias[cg + 1];
                {
                    long long idx = bz * sO + (long long)r0 * Ntot + cg;
                    const float2 rv = *(const float2*)(residual + idx);
                    float2 v = { acc[mt][nt][0] + b0 + rv.x,
                                 acc[mt][nt][1] + b1 + rv.y };
                    *(float2*)((float*)Out + idx) = v;
                }
                {
                    long long idx = bz * sO + (long long)(r0 + 8) * Ntot + cg;
                    const float2 rv = *(const float2*)(residual + idx);
                    float2 v = { acc[mt][nt][2] + b0 + rv.x,
                                 acc[mt][nt][3] + b1 + rv.y };
                    *(float2*)((float*)Out + idx) = v;
                }
            }
        } else {
            __nv_bfloat16* op = (__nv_bfloat16*)Out + bz * sO;
#pragma unroll
            for (int nt = 0; nt < 8; nt++) {
                const int cg = bx * 128 + warp_n * 64 + nt * 8 + tig * 2;
                float b0 = bias[cg], b1 = bias[cg + 1];
                *(__nv_bfloat162*)(op + (long long)r0 * Ntot + cg) =
                    __floats2bfloat162_rn(acc[mt][nt][0] + b0, acc[mt][nt][1] + b1);
                *(__nv_bfloat162*)(op + (long long)(r0 + 8) * Ntot + cg) =
                    __floats2bfloat162_rn(acc[mt][nt][2] + b0, acc[mt][nt][3] + b1);
            }
        }
    }
}

// ---------------- PDL launch helper ----------------
template<typename... Args>
static void launch_pdl(void (*kern)(Args...), dim3 grid, dim3 block, size_t smem,
                       Args... args)
{
    cudaLaunchConfig_t cfg = {};
    cfg.gridDim = grid;
    cfg.blockDim = block;
    cfg.dynamicSmemBytes = smem;
    cudaLaunchAttribute attr[1];
    attr[0].id = cudaLaunchAttributeProgrammaticStreamSerialization;
    attr[0].val.programmaticStreamSerializationAllowed = 1;
    cfg.attrs = attr;
    cfg.numAttrs = 1;
    cudaLaunchKernelEx(&cfg, kern, args...);
}

// ---------------- launch ----------------
extern "C" void kernel_launch(void* const* d_in, const int* in_sizes, int n_in,
                              void* d_out, int out_size)
{
    const float* x  = (const float*)d_in[0];
    const float* ns = (const float*)d_in[1];
    const float* nb = (const float*)d_in[2];
    const float* wq = (const float*)d_in[3];
    const float* bq = (const float*)d_in[4];
    const float* wk = (const float*)d_in[5];
    const float* bk = (const float*)d_in[6];
    const float* wv = (const float*)d_in[7];
    const float* bv = (const float*)d_in[8];
    const float* wp = (const float*)d_in[9];
    const float* bp = (const float*)d_in[10];
    float* out = (float*)d_out;

    __nv_bfloat16 *hn, *qkv, *s, *o, *wqkvB, *wpB;
    float *bqkv, *rs;
    cudaGetSymbolAddress((void**)&hn,    g_hn);
    cudaGetSymbolAddress((void**)&qkv,   g_qkv);
    cudaGetSymbolAddress((void**)&s,     g_s);
    cudaGetSymbolAddress((void**)&o,     g_o);
    cudaGetSymbolAddress((void**)&wqkvB, g_wqkv);
    cudaGetSymbolAddress((void**)&wpB,   g_wp);
    cudaGetSymbolAddress((void**)&bqkv,  g_bqkv);
    cudaGetSymbolAddress((void**)&rs,    g_rowsum);

    const int SMEM = NSTG * STAGE;   // 110592
    cudaFuncSetAttribute(mma_gemm<true, 0>,  cudaFuncAttributeMaxDynamicSharedMemorySize, SMEM);
    cudaFuncSetAttribute(mma_gemm<false, 1>, cudaFuncAttributeMaxDynamicSharedMemorySize, SMEM);
    cudaFuncSetAttribute(mma_gemm<true, 2>,  cudaFuncAttributeMaxDynamicSharedMemorySize, SMEM);
    cudaFuncSetAttribute(mma_gemm<true, 3>,  cudaFuncAttributeMaxDynamicSharedMemorySize, SMEM);

    // merged prologue + groupnorm (one launch; gn blocks first = long pole)
    pro_gn_kernel<<<1664, 256>>>(x, ns, nb, hn,
                                 wq, wk, wv, wqkvB,
                                 bq, bk, bv, bqkv,
                                 wp, wpB, rs);

    const __nv_bfloat16* q = qkv;
    const __nv_bfloat16* k = qkv + 512;
    const __nv_bfloat16* v = qkv + 1024;
    const long long sQKV = (long long)HW * NQKV;

    // fused qkv projection: [32768,512] @ [512,1536]
    launch_pdl(mma_gemm<true, 0>, dim3(NQKV / 128, M_TOT / 128, 1), dim3(256), (size_t)SMEM,
               (const __nv_bfloat16*)hn, (const __nv_bfloat16*)wqkvB,
               (const float*)bqkv, (const float*)nullptr, (float*)nullptr,
               (void*)qkv, (int)C, (int)C, (int)NQKV, (int)NQKV,
               1.f, 0LL, 0LL, 0LL);

    // exp-scores = 2^(q @ k^T * c^-0.5 * log2e), rowsum via atomics (bare MUFU.EX2)
    const float sc_log2e = (1.f / sqrtf((float)C)) * 1.4426950408889634f;
    launch_pdl(mma_gemm<false, 1>, dim3(HW / 128, HW / 128, BATCH), dim3(256), (size_t)SMEM,
               q, k, (const float*)nullptr, (const float*)nullptr, rs,
               (void*)s, (int)C, (int)NQKV, (int)NQKV, (int)HW,
               sc_log2e, sQKV, sQKV, (long long)HW * HW);

    // o = (expS @ v) / Z
    launch_pdl(mma_gemm<true, 3>, dim3(C / 128, HW / 128, BATCH), dim3(256), (size_t)SMEM,
               (const __nv_bfloat16*)s, v, (const float*)nullptr, (const float*)nullptr, rs,
               (void*)o, (int)HW, (int)HW, (int)NQKV, (int)C,
               1.f, (long long)HW * HW, sQKV, (long long)HW * C);

    // out = o @ wp + bp + x
    launch_pdl(mma_gemm<true, 2>, dim3(C / 128, M_TOT / 128, 1), dim3(256), (size_t)SMEM,
               (const __nv_bfloat16*)o, (const __nv_bfloat16*)wpB,
               bp, x, (float*)nullptr,
               (void*)out, (int)C, (int)C, (int)C, (int)C,
               1.f, 0LL, 0LL, 0LL);
}

// round 16
// speedup vs baseline: 1.0215x; 1.0099x over previous
#include <cuda_runtime.h>
#include <cuda_bf16.h>
#include <cstdint>
#include <math.h>

// ---------------- problem constants ----------------
#define BATCH 32
#define HW    1024
#define C     512
#define GROUPS 32
#define CPG   16
#define M_TOT (BATCH*HW)       // 32768
#define EPS   1e-6f
#define NQKV  1536

// ---------------- scratch ----------------
__device__ __nv_bfloat16 g_hn  [(long long)M_TOT * C];
__device__ __nv_bfloat16 g_qkv [(long long)M_TOT * NQKV];    // [row][q|k|v]
__device__ __nv_bfloat16 g_s   [(long long)BATCH * HW * HW]; // exp(scores), unnormalized
__device__ __nv_bfloat16 g_o   [(long long)M_TOT * C];
__device__ __nv_bfloat16 g_wqkv[(long long)C * NQKV];        // [k][q|k|v]
__device__ __nv_bfloat16 g_wp  [(long long)C * C];
__device__ float g_bqkv[NQKV];
__device__ float g_rowsum[BATCH * HW];

// ---------------- helpers ----------------
__device__ __forceinline__ uint32_t smem_u32(const void* p) {
    uint32_t a;
    asm("{ .reg .u64 t; cvta.to.shared.u64 t, %1; cvt.u32.u64 %0, t; }" : "=r"(a) : "l"(p));
    return a;
}
__device__ __forceinline__ void pdl_wait() {
#if __CUDA_ARCH__ >= 900
    cudaGridDependencySynchronize();
#endif
}
__device__ __forceinline__ void pdl_trigger() {
#if __CUDA_ARCH__ >= 900
    cudaTriggerProgrammaticLaunchCompletion();
#endif
}
#define LDSM_X4(r0,r1,r2,r3,addr) \
    asm volatile("ldmatrix.sync.aligned.m8n8.x4.shared.b16 {%0,%1,%2,%3}, [%4];" \
        : "=r"(r0),"=r"(r1),"=r"(r2),"=r"(r3) : "r"(addr))
#define LDSM_X4T(r0,r1,r2,r3,addr) \
    asm volatile("ldmatrix.sync.aligned.m8n8.x4.trans.shared.b16 {%0,%1,%2,%3}, [%4];" \
        : "=r"(r0),"=r"(r1),"=r"(r2),"=r"(r3) : "r"(addr))
#define MMA_BF16(d, a, b) \
    asm volatile("mma.sync.aligned.m16n8k16.row.col.f32.bf16.bf16.f32 " \
        "{%0,%1,%2,%3}, {%4,%5,%6,%7}, {%8,%9}, {%0,%1,%2,%3};" \
        : "+f"((d)[0]), "+f"((d)[1]), "+f"((d)[2]), "+f"((d)[3]) \
        : "r"((a)[0]), "r"((a)[1]), "r"((a)[2]), "r"((a)[3]), "r"((b)[0]), "r"((b)[1]))
#define CP_ASYNC16(smem, gmem) \
    asm volatile("cp.async.cg.shared.global [%0], [%1], 16;" :: "r"(smem), "l"(gmem))
#define CP_COMMIT() asm volatile("cp.async.commit_group;" ::: "memory")
#define CP_WAIT1()  asm volatile("cp.async.wait_group 1;" ::: "memory")

// ---------------- merged prologue + groupnorm ----------------
__global__ __launch_bounds__(256)
void pro_gn_kernel(const float* __restrict__ x, const float* __restrict__ scale,
                   const float* __restrict__ bias, __nv_bfloat16* __restrict__ hn,
                   const float* __restrict__ wq, const float* __restrict__ wk,
                   const float* __restrict__ wv, __nv_bfloat16* __restrict__ wqkvo,
                   const float* __restrict__ bq, const float* __restrict__ bk,
                   const float* __restrict__ bv, float* __restrict__ bqkv,
                   const float* __restrict__ wp, __nv_bfloat16* __restrict__ wpo,
                   float* __restrict__ rs)
{
    const int blk = blockIdx.x;
    const int tid = threadIdx.x;
    if (blk < 512) {
        // ---- groupnorm over a 32-channel pair ----
        const int b = blk >> 4, gp = blk & 15;
        const float4* base4 = reinterpret_cast<const float4*>(x + (long long)b * HW * C + gp * 32);
        const int lane = tid & 31, wid = tid >> 5;
        const int grp = (tid >> 2) & 1;

        float s = 0.f, s2 = 0.f;
        for (int e = tid; e < HW * 8; e += 256) {
            int p = e >> 3, cc = e & 7;
            float4 v = base4[(long long)p * 128 + cc];
            s  += v.x + v.y + v.z + v.w;
            s2 += v.x * v.x + v.y * v.y + v.z * v.z + v.w * v.w;
        }
        s  += __shfl_xor_sync(0xffffffffu, s, 1);
        s2 += __shfl_xor_sync(0xffffffffu, s2, 1);
        s  += __shfl_xor_sync(0xffffffffu, s, 2);
        s2 += __shfl_xor_sync(0xffffffffu, s2, 2);
        s  += __shfl_xor_sync(0xffffffffu, s, 8);
        s2 += __shfl_xor_sync(0xffffffffu, s2, 8);
        s  += __shfl_xor_sync(0xffffffffu, s, 16);
        s2 += __shfl_xor_sync(0xffffffffu, s2, 16);

        __shared__ float red[2][2][8];
        __shared__ float mr[2][2];
        if (lane == 0)      { red[0][0][wid] = s; red[0][1][wid] = s2; }
        else if (lane == 4) { red[1][0][wid] = s; red[1][1][wid] = s2; }
        __syncthreads();
        if (tid < 2) {
            float ss = 0.f, ss2 = 0.f;
#pragma unroll
            for (int w = 0; w < 8; w++) { ss += red[tid][0][w]; ss2 += red[tid][1][w]; }
            float m = ss * (1.f / (HW * CPG));
            float var = ss2 * (1.f / (HW * CPG)) - m * m;
            mr[tid][0] = m; mr[tid][1] = rsqrtf(var + EPS);
        }
        __syncthreads();
        const float m = mr[grp][0], r = mr[grp][1];

        __nv_bfloat16* hbase = hn + (long long)b * HW * C + gp * 32;
        for (int e = tid; e < HW * 8; e += 256) {
            int p = e >> 3, cc = e & 7;
            float4 v  = base4[(long long)p * 128 + cc];
            float4 sc = reinterpret_cast<const float4*>(scale)[gp * 8 + cc];
            float4 bi = reinterpret_cast<const float4*>(bias)[gp * 8 + cc];
            __nv_bfloat162 h0 = __floats2bfloat162_rn((v.x - m) * r * sc.x + bi.x, (v.y - m) * r * sc.y + bi.y);
            __nv_bfloat162 h1 = __floats2bfloat162_rn((v.z - m) * r * sc.z + bi.z, (v.w - m) * r * sc.w + bi.w);
            __nv_bfloat162* hp = reinterpret_cast<__nv_bfloat162*>(hbase + (long long)p * C + cc * 4);
            hp[0] = h0; hp[1] = h1;
        }
    } else if (blk < 1280) {
        int i = (blk - 512) * 256 + tid;               // float4 over [512][1536]
        int row = i / (NQKV / 4);
        int col = (i % (NQKV / 4)) * 4;
        int sel = col >> 9;
        const float* src = (sel == 0) ? wq : (sel == 1) ? wk : wv;
        float4 v = *reinterpret_cast<const float4*>(src + (long long)row * C + (col & 511));
        __nv_bfloat162* h2 = reinterpret_cast<__nv_bfloat162*>(wqkvo) + i * 2;
        h2[0] = __floats2bfloat162_rn(v.x, v.y);
        h2[1] = __floats2bfloat162_rn(v.z, v.w);
    } else if (blk < 1536) {
        int i = (blk - 1280) * 256 + tid;              // float4 over [512][512]
        float4 v = reinterpret_cast<const float4*>(wp)[i];
        __nv_bfloat162* h2 = reinterpret_cast<__nv_bfloat162*>(wpo) + i * 2;
        h2[0] = __floats2bfloat162_rn(v.x, v.y);
        h2[1] = __floats2bfloat162_rn(v.z, v.w);
        if (i < NQKV) {
            int sel = i >> 9;
            const float* src = (sel == 0) ? bq : (sel == 1) ? bk : bv;
            bqkv[i] = src[i & 511];
        }
    } else {
        int i = (blk - 1536) * 256 + tid;
        if (i < BATCH * HW) rs[i] = 0.f;
    }
    pdl_trigger();
}

// ---------------- HMMA GEMM, compile-time shapes ----------------
// template: TB (B transposed=NN via ldmatrix.trans), MODE, K, LDA, LDB, NTOT.
// MODE 0: bf16 out + bias.          MODE 1: bf16 out = expf(acc*scale) + rowsum atomics.
// MODE 2: fp32 out + bias + residual.  MODE 3: bf16 out = acc / rowsum[row].
#define A_STRIDE 144u
#define BNN_STRIDE 272u
#define BOFF  18432u
#define STAGE 36864u
#define NSTG  3

template<bool TB, int MODE, int K, int LDA, int LDB, int NTOT>
__global__ void __launch_bounds__(256, 2)
mma_gemm(const __nv_bfloat16* __restrict__ A, const __nv_bfloat16* __restrict__ B,
         const float* __restrict__ bias, const float* __restrict__ residual,
         float* __restrict__ rowsum,
         void* __restrict__ Out, float scale,
         long long sA, long long sB, long long sO)
{
    extern __shared__ char dyn[];
    const uint32_t smem0 = smem_u32(dyn);
    const uint32_t smemEnd = smem0 + NSTG * STAGE;

    const int tid = threadIdx.x, lane = tid & 31, wid = tid >> 5;
    const int warp_m = wid & 3, warp_n = wid >> 2;
    const int bx = blockIdx.x, by = blockIdx.y, bz = blockIdx.z;

    constexpr int NC = K >> 6;

    float acc[2][8][4];
#pragma unroll
    for (int mt = 0; mt < 2; mt++)
#pragma unroll
        for (int nt = 0; nt < 8; nt++)
#pragma unroll
            for (int e = 0; e < 4; e++) acc[mt][nt][e] = 0.f;

    // ----- incremental global pointers (compile-time strides) -----
    const char* pA = (const char*)(A + bz * sA)
                   + ((long long)(by * 128 + (tid >> 3)) * LDA) * 2 + (tid & 7) * 16;
    constexpr long long aRep = 32LL * LDA * 2;        // +32 rows
    const char* pB;
    if (TB) {
        pB = (const char*)(B + bz * sB) + ((long long)(tid >> 4) * LDB + bx * 128) * 2 + (tid & 15) * 16;
    } else {
        pB = (const char*)(B + bz * sB) + ((long long)(bx * 128 + (tid >> 3)) * LDB) * 2 + (tid & 7) * 16;
    }
    constexpr long long bRep = TB ? 16LL * LDB * 2 : 32LL * LDB * 2;
    constexpr long long aAdv = 128;                    // bytes per k-chunk
    constexpr long long bAdv = TB ? 64LL * LDB * 2 : 128LL;

    // ----- smem store offsets (per-thread constants) -----
    const uint32_t sAoff = (uint32_t)(tid >> 3) * A_STRIDE + (uint32_t)(tid & 7) * 16;
    const uint32_t sBoff = TB
        ? BOFF + (uint32_t)(tid >> 4) * BNN_STRIDE + (uint32_t)(tid & 15) * 16
        : BOFF + (uint32_t)(tid >> 3) * A_STRIDE + (uint32_t)(tid & 7) * 16;
    constexpr uint32_t sBrep = TB ? 16u * BNN_STRIDE : 32u * A_STRIDE;

    uint32_t stLd = smem0;    // stage base for next load
    auto load_chunk = [&]() {
#pragma unroll
        for (int rep = 0; rep < 4; rep++)
            CP_ASYNC16(stLd + sAoff + (uint32_t)rep * (32u * A_STRIDE), pA + rep * aRep);
#pragma unroll
        for (int rep = 0; rep < 4; rep++)
            CP_ASYNC16(stLd + sBoff + (uint32_t)rep * sBrep, pB + rep * bRep);
        CP_COMMIT();
        pA += aAdv; pB += bAdv;
        stLd += STAGE; if (stLd == smemEnd) stLd = smem0;
    };

    // PDL: block until upstream writes are visible, then start loading.
    pdl_wait();

    load_chunk();
    load_chunk();

    const int lan15 = lane & 15;
    const int hi8   = (lane >> 4) << 3;

    uint32_t smCur = smem0;
    for (int i = 0; i < NC; ++i) {
        CP_WAIT1();
        __syncthreads();
        const uint32_t smA = smCur;
        const uint32_t smB = smCur + BOFF;
#pragma unroll
        for (int ks = 0; ks < 4; ks++) {
            uint32_t a[2][4];
#pragma unroll
            for (int mt = 0; mt < 2; mt++) {
                uint32_t ad = smA + (uint32_t)(warp_m * 32 + mt * 16 + lan15) * A_STRIDE
                                  + (uint32_t)(ks * 16 + hi8) * 2;
                LDSM_X4(a[mt][0], a[mt][1], a[mt][2], a[mt][3], ad);
            }
            uint32_t b[8][2];
            if (TB) {
#pragma unroll
                for (int np = 0; np < 4; np++) {
                    uint32_t ad = smB + (uint32_t)(ks * 16 + lan15) * BNN_STRIDE
                                      + (uint32_t)(warp_n * 64 + np * 16 + hi8) * 2;
                    uint32_t r0, r1, r2, r3;
                    LDSM_X4T(r0, r1, r2, r3, ad);
                    b[2*np][0] = r0; b[2*np][1] = r1;
                    b[2*np+1][0] = r2; b[2*np+1][1] = r3;
                }
            } else {
#pragma unroll
                for (int np = 0; np < 4; np++) {
                    uint32_t ad = smB + (uint32_t)(warp_n * 64 + np * 16 + lan15) * A_STRIDE
                                      + (uint32_t)(ks * 16 + hi8) * 2;
                    uint32_t r0, r1, r2, r3;
                    LDSM_X4(r0, r1, r2, r3, ad);
                    b[2*np][0] = r0; b[2*np][1] = r2;
                    b[2*np+1][0] = r1; b[2*np+1][1] = r3;
                }
            }
#pragma unroll
            for (int mt = 0; mt < 2; mt++)
#pragma unroll
                for (int nt = 0; nt < 8; nt++)
                    MMA_BF16(acc[mt][nt], a[mt], b[nt]);
        }
        smCur += STAGE; if (smCur == smemEnd) smCur = smem0;
        // load AFTER compute (R9 proven ordering)
        if (i + 2 < NC) load_chunk();
        else CP_COMMIT();
    }

    // allow the dependent kernel to launch while epilogues run
    pdl_trigger();

    // ---------------- epilogue (direct stores, compile-time NTOT) ----------------
    const int group = lane >> 2, tig = lane & 3;
#pragma unroll
    for (int mt = 0; mt < 2; mt++) {
        const int r0 = by * 128 + warp_m * 32 + mt * 16 + group;
        if (MODE == 1) {
            __nv_bfloat16* op = (__nv_bfloat16*)Out + bz * sO;
            float rs0 = 0.f, rs1 = 0.f;
#pragma unroll
            for (int nt = 0; nt < 8; nt++) {
                const int cg = bx * 128 + warp_n * 64 + nt * 8 + tig * 2;
                float e0 = __expf(acc[mt][nt][0] * scale);
                float e1 = __expf(acc[mt][nt][1] * scale);
                float e2 = __expf(acc[mt][nt][2] * scale);
                float e3 = __expf(acc[mt][nt][3] * scale);
                *(__nv_bfloat162*)(op + (long long)r0 * NTOT + cg)       = __floats2bfloat162_rn(e0, e1);
                *(__nv_bfloat162*)(op + (long long)(r0 + 8) * NTOT + cg) = __floats2bfloat162_rn(e2, e3);
                rs0 += e0 + e1; rs1 += e2 + e3;
            }
            rs0 += __shfl_xor_sync(0xffffffffu, rs0, 1);
            rs0 += __shfl_xor_sync(0xffffffffu, rs0, 2);
            rs1 += __shfl_xor_sync(0xffffffffu, rs1, 1);
            rs1 += __shfl_xor_sync(0xffffffffu, rs1, 2);
            if (tig == 0) {
                atomicAdd(rowsum + bz * HW + r0, rs0);
                atomicAdd(rowsum + bz * HW + r0 + 8, rs1);
            }
        } else if (MODE == 3) {
            const float inv0 = 1.f / rowsum[bz * HW + r0];
            const float inv1 = 1.f / rowsum[bz * HW + r0 + 8];
            __nv_bfloat16* op = (__nv_bfloat16*)Out + bz * sO;
#pragma unroll
            for (int nt = 0; nt < 8; nt++) {
                const int cg = bx * 128 + warp_n * 64 + nt * 8 + tig * 2;
                *(__nv_bfloat162*)(op + (long long)r0 * NTOT + cg) =
                    __floats2bfloat162_rn(acc[mt][nt][0] * inv0, acc[mt][nt][1] * inv0);
                *(__nv_bfloat162*)(op + (long long)(r0 + 8) * NTOT + cg) =
                    __floats2bfloat162_rn(acc[mt][nt][2] * inv1, acc[mt][nt][3] * inv1);
            }
        } else if (MODE == 2) {
#pragma unroll
            for (int nt = 0; nt < 8; nt++) {
                const int cg = bx * 128 + warp_n * 64 + nt * 8 + tig * 2;
                float b0 = bias[cg], b1 = bias[cg + 1];
                {
                    long long idx = bz * sO + (long long)r0 * NTOT + cg;
                    const float2 rv = *(const float2*)(residual + idx);
                    float2 v = { acc[mt][nt][0] + b0 + rv.x,
                                 acc[mt][nt][1] + b1 + rv.y };
                    *(float2*)((float*)Out + idx) = v;
                }
                {
                    long long idx = bz * sO + (long long)(r0 + 8) * NTOT + cg;
                    const float2 rv = *(const float2*)(residual + idx);
                    float2 v = { acc[mt][nt][2] + b0 + rv.x,
                                 acc[mt][nt][3] + b1 + rv.y };
                    *(float2*)((float*)Out + idx) = v;
                }
            }
        } else {
            __nv_bfloat16* op = (__nv_bfloat16*)Out + bz * sO;
#pragma unroll
            for (int nt = 0; nt < 8; nt++) {
                const int cg = bx * 128 + warp_n * 64 + nt * 8 + tig * 2;
                float b0 = bias[cg], b1 = bias[cg + 1];
                *(__nv_bfloat162*)(op + (long long)r0 * NTOT + cg) =
                    __floats2bfloat162_rn(acc[mt][nt][0] + b0, acc[mt][nt][1] + b1);
                *(__nv_bfloat162*)(op + (long long)(r0 + 8) * NTOT + cg) =
                    __floats2bfloat162_rn(acc[mt][nt][2] + b0, acc[mt][nt][3] + b1);
            }
        }
    }
}

// ---------------- PDL launch helper ----------------
template<typename... Args>
static void launch_pdl(void (*kern)(Args...), dim3 grid, dim3 block, size_t smem,
                       Args... args)
{
    cudaLaunchConfig_t cfg = {};
    cfg.gridDim = grid;
    cfg.blockDim = block;
    cfg.dynamicSmemBytes = smem;
    cudaLaunchAttribute attr[1];
    attr[0].id = cudaLaunchAttributeProgrammaticStreamSerialization;
    attr[0].val.programmaticStreamSerializationAllowed = 1;
    cfg.attrs = attr;
    cfg.numAttrs = 1;
    cudaLaunchKernelEx(&cfg, kern, args...);
}

// ---------------- launch ----------------
extern "C" void kernel_launch(void* const* d_in, const int* in_sizes, int n_in,
                              void* d_out, int out_size)
{
    const float* x  = (const float*)d_in[0];
    const float* ns = (const float*)d_in[1];
    const float* nb = (const float*)d_in[2];
    const float* wq = (const float*)d_in[3];
    const float* bq = (const float*)d_in[4];
    const float* wk = (const float*)d_in[5];
    const float* bk = (const float*)d_in[6];
    const float* wv = (const float*)d_in[7];
    const float* bv = (const float*)d_in[8];
    const float* wp = (const float*)d_in[9];
    const float* bp = (const float*)d_in[10];
    float* out = (float*)d_out;

    __nv_bfloat16 *hn, *qkv, *s, *o, *wqkvB, *wpB;
    float *bqkv, *rs;
    cudaGetSymbolAddress((void**)&hn,    g_hn);
    cudaGetSymbolAddress((void**)&qkv,   g_qkv);
    cudaGetSymbolAddress((void**)&s,     g_s);
    cudaGetSymbolAddress((void**)&o,     g_o);
    cudaGetSymbolAddress((void**)&wqkvB, g_wqkv);
    cudaGetSymbolAddress((void**)&wpB,   g_wp);
    cudaGetSymbolAddress((void**)&bqkv,  g_bqkv);
    cudaGetSymbolAddress((void**)&rs,    g_rowsum);

    const int SMEM = NSTG * STAGE;   // 110592

    auto kQKV   = mma_gemm<true,  0, 512,  512,  1536, 1536>;
    auto kSCORE = mma_gemm<false, 1, 512,  1536, 1536, 1024>;
    auto kPV    = mma_gemm<true,  3, 1024, 1024, 1536, 512>;
    auto kFINAL = mma_gemm<true,  2, 512,  512,  512,  512>;

    cudaFuncSetAttribute(kQKV,   cudaFuncAttributeMaxDynamicSharedMemorySize, SMEM);
    cudaFuncSetAttribute(kSCORE, cudaFuncAttributeMaxDynamicSharedMemorySize, SMEM);
    cudaFuncSetAttribute(kPV,    cudaFuncAttributeMaxDynamicSharedMemorySize, SMEM);
    cudaFuncSetAttribute(kFINAL, cudaFuncAttributeMaxDynamicSharedMemorySize, SMEM);

    // merged prologue + groupnorm (one launch; gn blocks first = long pole)
    pro_gn_kernel<<<1664, 256>>>(x, ns, nb, hn,
                                 wq, wk, wv, wqkvB,
                                 bq, bk, bv, bqkv,
                                 wp, wpB, rs);

    const __nv_bfloat16* q = qkv;
    const __nv_bfloat16* k = qkv + 512;
    const __nv_bfloat16* v = qkv + 1024;
    const long long sQKV = (long long)HW * NQKV;

    // fused qkv projection: [32768,512] @ [512,1536]
    launch_pdl(kQKV, dim3(NQKV / 128, M_TOT / 128, 1), dim3(256), (size_t)SMEM,
               (const __nv_bfloat16*)hn, (const __nv_bfloat16*)wqkvB,
               (const float*)bqkv, (const float*)nullptr, (float*)nullptr,
               (void*)qkv, 1.f, 0LL, 0LL, 0LL);

    // exp-scores = exp(q @ k^T * c^-0.5), rowsum via atomics
    launch_pdl(kSCORE, dim3(HW / 128, HW / 128, BATCH), dim3(256), (size_t)SMEM,
               q, k, (const float*)nullptr, (const float*)nullptr, rs,
               (void*)s, 1.f / sqrtf((float)C), sQKV, sQKV, (long long)HW * HW);

    // o = (expS @ v) / Z
    launch_pdl(kPV, dim3(C / 128, HW / 128, BATCH), dim3(256), (size_t)SMEM,
               (const __nv_bfloat16*)s, v, (const float*)nullptr, (const float*)nullptr, rs,
               (void*)o, 1.f, (long long)HW * HW, sQKV, (long long)HW * C);

    // out = o @ wp + bp + x
    launch_pdl(kFINAL, dim3(C / 128, M_TOT / 128, 1), dim3(256), (size_t)SMEM,
               (const __nv_bfloat16*)o, (const __nv_bfloat16*)wpB,
               bp, x, (float*)nullptr,
               (void*)out, 1.f, 0LL, 0LL, 0LL);
}